// round 14
// baseline (speedup 1.0000x reference)
#include <cuda_runtime.h>
#include <cstdint>

// out[s,:] = W_tok[x[s],:] + b_tok + W_pos[(S-1)-s,:] + b_pos
// S=8192, D=1024 fp32.
// R11: R7 persistent single-wave chassis + depth-4 cp.async SMEM pipeline.
// Breaks the pipeline-depth <-> register-pressure coupling that killed R9:
// in-flight rows live in SMEM (32KB/CTA), regs stay ~30. Each thread copies
// and consumes only its own 16B chunk -> per-thread cp.async.wait_group,
// NO __syncthreads in the loop. .cg bypasses L1 (zero-reuse gather).

constexpr int SEQ   = 8192;
constexpr int EMBED = 1024;
constexpr int VEC   = EMBED / 4;   // 256 float4 per row
constexpr int GRID  = 888;         // 148 SMs x 6 CTAs -> one wave
constexpr int DEPTH = 4;           // pipeline stages (8KB smem each)

__device__ __forceinline__ void cp16(float4* dst_smem, const float4* src) {
    uint32_t d = (uint32_t)__cvta_generic_to_shared(dst_smem);
    asm volatile("cp.async.cg.shared.global [%0], [%1], 16;"
                 :: "r"(d), "l"(src) : "memory");
}
__device__ __forceinline__ void cp_commit() {
    asm volatile("cp.async.commit_group;" ::: "memory");
}
template <int N> __device__ __forceinline__ void cp_wait() {
    asm volatile("cp.async.wait_group %0;" :: "n"(N) : "memory");
}

__global__ __launch_bounds__(256, 6)
void linear_embedding_kernel(const int* __restrict__ x,
                             const float4* __restrict__ W_tok,
                             const float4* __restrict__ b_tok,
                             const float4* __restrict__ W_pos,
                             const float4* __restrict__ b_pos,
                             float4* __restrict__ out)
{
    __shared__ float4 tok_s[DEPTH][VEC];   // 16KB
    __shared__ float4 pos_s[DEPTH][VEC];   // 16KB

    const int t      = threadIdx.x;
    const int stride = GRID;

    // Bias for this thread's column (zeros in practice; cache-resident).
    const float4 bt = __ldg(&b_tok[t]);
    const float4 bp = __ldg(&b_pos[t]);
    float4 b;
    b.x = bt.x + bp.x; b.y = bt.y + bp.y;
    b.z = bt.z + bp.z; b.w = bt.w + bp.w;

    int s = blockIdx.x;

    // Prologue: fill all DEPTH stages (stage j covers row s + j*stride).
#pragma unroll
    for (int j = 0; j < DEPTH; ++j) {
        const int sj   = min(s + j * stride, SEQ - 1);
        const int tokj = __ldg(&x[sj]);
        cp16(&tok_s[j][t], &W_tok[(long long)tokj * VEC + t]);
        cp16(&pos_s[j][t], &W_pos[(long long)(SEQ - 1 - sj) * VEC + t]);
        cp_commit();
    }
    // Token id for the next stage to be issued (s + DEPTH*stride).
    int tok_pre = __ldg(&x[min(s + DEPTH * stride, SEQ - 1)]);

    int stage = 0;
    while (s < SEQ) {
        // Oldest group (this stage) complete; DEPTH-1 groups stay in flight.
        cp_wait<DEPTH - 1>();
        const float4 a = tok_s[stage][t];
        const float4 p = pos_s[stage][t];

        float4 r;
        r.x = (a.x + p.x) + b.x;
        r.y = (a.y + p.y) + b.y;
        r.z = (a.z + p.z) + b.z;
        r.w = (a.w + p.w) + b.w;
        out[(long long)s * VEC + t] = r;

        // Refill this slot with row s + DEPTH*stride (clamped; tail dupes harmless).
        const int sn = min(s + DEPTH * stride, SEQ - 1);
        cp16(&tok_s[stage][t], &W_tok[(long long)tok_pre * VEC + t]);
        cp16(&pos_s[stage][t], &W_pos[(long long)(SEQ - 1 - sn) * VEC + t]);
        cp_commit();
        tok_pre = __ldg(&x[min(s + (DEPTH + 1) * stride, SEQ - 1)]);

        s += stride;
        stage = (stage + 1 == DEPTH) ? 0 : stage + 1;
    }
}

extern "C" void kernel_launch(void* const* d_in, const int* in_sizes, int n_in,
                              void* d_out, int out_size)
{
    const int*    x     = (const int*)d_in[0];
    const float4* W_tok = (const float4*)d_in[1];
    const float4* b_tok = (const float4*)d_in[2];
    const float4* W_pos = (const float4*)d_in[3];
    const float4* b_pos = (const float4*)d_in[4];
    float4* out = (float4*)d_out;

    linear_embedding_kernel<<<GRID, 256>>>(x, W_tok, b_tok, W_pos, b_pos, out);
}